// round 11
// baseline (speedup 1.0000x reference)
#include <cuda_runtime.h>
#include <cfloat>

#define NSETS  8
#define NPTS   4096
#define DF     16
#define KK     16
#define TPB    256
#define WPB    (TPB / 32)       // 8 warps
#define QPW    4                // queries per warp
#define QPC    (WPB * QPW)      // 32 queries per CTA
#define TILE   256
#define ROWP   20               // padded row stride: conflict-free LDS.128

__device__ __forceinline__ unsigned long long pack2(float lo, float hi) {
    unsigned long long r;
    asm("mov.b64 %0, {%1, %2};" : "=l"(r) : "f"(lo), "f"(hi));
    return r;
}
__device__ __forceinline__ void unpack2(unsigned long long v, float& lo, float& hi) {
    asm("mov.b64 {%0, %1}, %2;" : "=f"(lo), "=f"(hi) : "l"(v));
}
__device__ __forceinline__ void fma2(unsigned long long& d, unsigned long long a, unsigned long long b) {
    asm("fma.rn.f32x2 %0, %1, %2, %0;" : "+l"(d) : "l"(a), "l"(b));
}
__device__ __forceinline__ unsigned long long mul2(unsigned long long a, unsigned long long b) {
    unsigned long long d;
    asm("mul.rn.f32x2 %0, %1, %2;" : "=l"(d) : "l"(a), "l"(b));
    return d;
}
__device__ __forceinline__ unsigned long long add2(unsigned long long a, unsigned long long b) {
    unsigned long long d;
    asm("add.rn.f32x2 %0, %1, %2;" : "=l"(d) : "l"(a), "l"(b));
    return d;
}

__device__ __forceinline__ void load_query(const float* __restrict__ xs, int row,
                                           unsigned long long (&qq)[8], float& qh) {
    const float4* qp = reinterpret_cast<const float4*>(xs + (size_t)row * DF);
    float4 q0 = qp[0], q1 = qp[1], q2 = qp[2], q3 = qp[3];
    qq[0] = pack2(q0.x, q0.y); qq[1] = pack2(q0.z, q0.w);
    qq[2] = pack2(q1.x, q1.y); qq[3] = pack2(q1.z, q1.w);
    qq[4] = pack2(q2.x, q2.y); qq[5] = pack2(q2.z, q2.w);
    qq[6] = pack2(q3.x, q3.y); qq[7] = pack2(q3.z, q3.w);
    float qn = q0.x*q0.x + q0.y*q0.y + q0.z*q0.z + q0.w*q0.w
             + q1.x*q1.x + q1.y*q1.y + q1.z*q1.z + q1.w*q1.w
             + q2.x*q2.x + q2.y*q2.y + q2.z*q2.z + q2.w*q2.w
             + q3.x*q3.x + q3.y*q3.y + q3.z*q3.z + q3.w*q3.w;
    qh = -0.5f * qn;
}

// s = dot(q,c) - 0.5||q||^2 - 0.5||c||^2   (dist = -2s; larger s = closer)
__device__ __forceinline__ float s_one(const unsigned long long (&qq)[8], float qh,
                                       ulonglong2 v0, ulonglong2 v1,
                                       ulonglong2 v2, ulonglong2 v3, float ch) {
    unsigned long long a0 = pack2(qh, ch);
    unsigned long long a1 = mul2(qq[1], v0.y);
    fma2(a0, qq[0], v0.x);
    fma2(a1, qq[3], v1.y);
    fma2(a0, qq[2], v1.x);
    fma2(a1, qq[5], v2.y);
    fma2(a0, qq[4], v2.x);
    fma2(a1, qq[7], v3.y);
    fma2(a0, qq[6], v3.x);
    unsigned long long s = add2(a0, a1);
    float lo, hi;
    unpack2(s, lo, hi);
    return lo + hi;
}

// paired drain in s-space: lanes 0..15 hold list for sLo's query, 16..31 for sHi's.
// Lists sorted DESCENDING in s (= ascending dist). Lazy threshold refresh.
__device__ __forceinline__ void drain_pair_s(float& ls, int& li,
                                             float sLo, float sHi,
                                             float& tLo, float& tHi,
                                             int idx0, bool loHalf, int lane) {
    const unsigned FULL = 0xFFFFFFFFu;
    unsigned ballA = __ballot_sync(FULL, sLo > tLo);
    unsigned ballB = __ballot_sync(FULL, sHi > tHi);
    if (!(ballA | ballB)) return;
    while (ballA | ballB) {
        const bool hasA = (ballA != 0), hasB = (ballB != 0);
        const int bA = hasA ? (__ffs(ballA) - 1) : 0;
        const int bB = hasB ? (__ffs(ballB) - 1) : 0;
        ballA &= ballA - 1;
        ballB &= ballB - 1;
        const float svA = __shfl_sync(FULL, sLo, bA);
        const float svB = __shfl_sync(FULL, sHi, bB);
        const float sv = loHalf ? svA : svB;
        const int   iv = idx0 + (loHalf ? bA : bB);
        const bool valid = loHalf ? hasA : hasB;
        const float pv = __shfl_up_sync(FULL, ls, 1);
        const int   pi = __shfl_up_sync(FULL, li, 1);
        const bool lt  = (ls < sv);                       // strict: ties keep earlier idx
        const bool plt = (lane != 0 && lane != KK) && (pv < sv);
        if (valid && lt) {
            ls = plt ? pv : sv;
            li = plt ? pi : iv;
        }
    }
    tLo = __shfl_sync(FULL, ls, KK - 1);
    tHi = __shfl_sync(FULL, ls, 31);
}

__global__ __launch_bounds__(TPB, 2)
void knn_warp4(const float* __restrict__ x, float* __restrict__ out,
               long long out_elems) {
    __shared__ float sc[TILE * ROWP];
    __shared__ float sch[TILE];

    const int tid  = threadIdx.x;
    const int lane = tid & 31;
    const int wid  = tid >> 5;
    const unsigned FULL = 0xFFFFFFFFu;

    const int qbase = blockIdx.x * QPC;
    const int q0r   = qbase + QPW * wid;
    const int set   = q0r / NPTS;
    const int row0  = q0r - set * NPTS;
    const float* __restrict__ xs = x + (size_t)set * NPTS * DF;

    unsigned long long qqA[8], qqB[8], qqC[8], qqD[8];
    float qhA, qhB, qhC, qhD;
    load_query(xs, row0 + 0, qqA, qhA);
    load_query(xs, row0 + 1, qqB, qhB);
    load_query(xs, row0 + 2, qqC, qhC);
    load_query(xs, row0 + 3, qqD, qhD);

    // layer1: lanes 0-15 = list A, lanes 16-31 = list B (s-space, descending)
    // layer2: lanes 0-15 = list C, lanes 16-31 = list D
    float l1_s = -FLT_MAX, l2_s = -FLT_MAX;
    int   l1_i = 0,        l2_i = 0;
    float thrA = -FLT_MAX, thrB = -FLT_MAX, thrC = -FLT_MAX, thrD = -FLT_MAX;
    const bool loHalf = (lane < KK);

    for (int j0 = 0; j0 < NPTS; j0 += TILE) {
        __syncthreads();
        {
            const float4* src = reinterpret_cast<const float4*>(xs + (size_t)(j0 + tid) * DF);
            float4 c0 = src[0], c1 = src[1], c2 = src[2], c3 = src[3];
            float* dst = sc + tid * ROWP;
            *reinterpret_cast<float4*>(dst)      = c0;
            *reinterpret_cast<float4*>(dst + 4)  = c1;
            *reinterpret_cast<float4*>(dst + 8)  = c2;
            *reinterpret_cast<float4*>(dst + 12) = c3;
            float n = c0.x*c0.x + c0.y*c0.y + c0.z*c0.z + c0.w*c0.w
                    + c1.x*c1.x + c1.y*c1.y + c1.z*c1.z + c1.w*c1.w
                    + c2.x*c2.x + c2.y*c2.y + c2.z*c2.z + c2.w*c2.w
                    + c3.x*c3.x + c3.y*c3.y + c3.z*c3.z + c3.w*c3.w;
            sch[tid] = -0.5f * n;
        }
        __syncthreads();

#pragma unroll
        for (int sub = 0; sub < TILE / 64; ++sub) {
            const int c0i = sub * 64 + lane;       // first candidate of this step
            // candidate 0
            {
            }
            const ulonglong2* cp0 = reinterpret_cast<const ulonglong2*>(sc + c0i * ROWP);
            ulonglong2 u0 = cp0[0], u1 = cp0[1], u2 = cp0[2], u3 = cp0[3];
            const float ch0 = sch[c0i];
            float sA0 = s_one(qqA, qhA, u0, u1, u2, u3, ch0);
            float sB0 = s_one(qqB, qhB, u0, u1, u2, u3, ch0);
            float sC0 = s_one(qqC, qhC, u0, u1, u2, u3, ch0);
            float sD0 = s_one(qqD, qhD, u0, u1, u2, u3, ch0);
            // candidate 1 (reuse u regs)
            const ulonglong2* cp1 = reinterpret_cast<const ulonglong2*>(sc + (c0i + 32) * ROWP);
            u0 = cp1[0]; u1 = cp1[1]; u2 = cp1[2]; u3 = cp1[3];
            const float ch1 = sch[c0i + 32];
            float sA1 = s_one(qqA, qhA, u0, u1, u2, u3, ch1);
            float sB1 = s_one(qqB, qhB, u0, u1, u2, u3, ch1);
            float sC1 = s_one(qqC, qhC, u0, u1, u2, u3, ch1);
            float sD1 = s_one(qqD, qhD, u0, u1, u2, u3, ch1);

            // single fast-path ballot over all 8 comparisons
            const bool anyhit = (sA0 > thrA) | (sB0 > thrB) | (sC0 > thrC) | (sD0 > thrD)
                              | (sA1 > thrA) | (sB1 > thrB) | (sC1 > thrC) | (sD1 > thrD);
            if (__ballot_sync(FULL, anyhit)) {
                const int idx0 = j0 + sub * 64;
                // candidate 0 drains first (lower indices) to preserve tie order
                drain_pair_s(l1_s, l1_i, sA0, sB0, thrA, thrB, idx0,      loHalf, lane);
                drain_pair_s(l2_s, l2_i, sC0, sD0, thrC, thrD, idx0,      loHalf, lane);
                drain_pair_s(l1_s, l1_i, sA1, sB1, thrA, thrB, idx0 + 32, loHalf, lane);
                drain_pair_s(l2_s, l2_i, sC1, sD1, thrC, thrD, idx0 + 32, loHalf, lane);
            }
        }
    }

    // write outputs directly (dist = -2 * s, identical float value to before)
    const long long E = (long long)NSETS * NPTS * KK;
    const int p    = loHalf ? lane : (lane - KK);
    const int qr1  = loHalf ? (q0r + 0) : (q0r + 1);
    const int qr2  = loHalf ? (q0r + 2) : (q0r + 3);
    const float d1 = -2.0f * l1_s;
    const float d2 = -2.0f * l2_s;
    if (out_elems >= 3 * E) {
        long long b1 = (long long)qr1 * KK + p;
        out[b1]         = (float)qr1;
        out[E + b1]     = (float)(set * NPTS + l1_i);
        out[2 * E + b1] = d1;
        long long b2 = (long long)qr2 * KK + p;
        out[b2]         = (float)qr2;
        out[E + b2]     = (float)(set * NPTS + l2_i);
        out[2 * E + b2] = d2;
    } else {
        out[(long long)qr1 * KK + p] = d1;
        out[(long long)qr2 * KK + p] = d2;
    }
}

extern "C" void kernel_launch(void* const* d_in, const int* in_sizes, int n_in,
                              void* d_out, int out_size) {
    const float* x = (const float*)d_in[0];
    float* out = (float*)d_out;
    knn_warp4<<<(NSETS * NPTS) / QPC, TPB>>>(x, out, (long long)out_size);
}

// round 14
// speedup vs baseline: 1.0547x; 1.0547x over previous
#include <cuda_runtime.h>
#include <cfloat>

#define NSETS  8
#define NPTS   4096
#define DF     16
#define KK     16
#define TPB    256
#define WPB    (TPB / 32)       // 8 warps
#define QPW    4                // queries per warp
#define QPC    (WPB * QPW)      // 32 queries per CTA
#define TILE   256
#define ROWP   20               // padded row stride: conflict-free LDS.128
#define SUBS   (TILE / 32)      // 8 warp-steps per tile

__device__ __forceinline__ unsigned long long pack2(float lo, float hi) {
    unsigned long long r;
    asm("mov.b64 %0, {%1, %2};" : "=l"(r) : "f"(lo), "f"(hi));
    return r;
}
__device__ __forceinline__ void unpack2(unsigned long long v, float& lo, float& hi) {
    asm("mov.b64 {%0, %1}, %2;" : "=f"(lo), "=f"(hi) : "l"(v));
}
__device__ __forceinline__ void fma2(unsigned long long& d, unsigned long long a, unsigned long long b) {
    asm("fma.rn.f32x2 %0, %1, %2, %0;" : "+l"(d) : "l"(a), "l"(b));
}
__device__ __forceinline__ unsigned long long mul2(unsigned long long a, unsigned long long b) {
    unsigned long long d;
    asm("mul.rn.f32x2 %0, %1, %2;" : "=l"(d) : "l"(a), "l"(b));
    return d;
}
__device__ __forceinline__ unsigned long long add2(unsigned long long a, unsigned long long b) {
    unsigned long long d;
    asm("add.rn.f32x2 %0, %1, %2;" : "=l"(d) : "l"(a), "l"(b));
    return d;
}

__device__ __forceinline__ void load_query(const float* __restrict__ xs, int row,
                                           unsigned long long (&qq)[8], float& qh) {
    const float4* qp = reinterpret_cast<const float4*>(xs + (size_t)row * DF);
    float4 q0 = qp[0], q1 = qp[1], q2 = qp[2], q3 = qp[3];
    qq[0] = pack2(q0.x, q0.y); qq[1] = pack2(q0.z, q0.w);
    qq[2] = pack2(q1.x, q1.y); qq[3] = pack2(q1.z, q1.w);
    qq[4] = pack2(q2.x, q2.y); qq[5] = pack2(q2.z, q2.w);
    qq[6] = pack2(q3.x, q3.y); qq[7] = pack2(q3.z, q3.w);
    float qn = q0.x*q0.x + q0.y*q0.y + q0.z*q0.z + q0.w*q0.w
             + q1.x*q1.x + q1.y*q1.y + q1.z*q1.z + q1.w*q1.w
             + q2.x*q2.x + q2.y*q2.y + q2.z*q2.z + q2.w*q2.w
             + q3.x*q3.x + q3.y*q3.y + q3.z*q3.z + q3.w*q3.w;
    qh = -0.5f * qn;
}

// s = dot(q,c) - 0.5||q||^2 - 0.5||c||^2   (dist = -2s; larger s = closer)
__device__ __forceinline__ float s_one(const unsigned long long (&qq)[8], float qh,
                                       ulonglong2 v0, ulonglong2 v1,
                                       ulonglong2 v2, ulonglong2 v3, float ch) {
    unsigned long long a0 = pack2(qh, ch);
    unsigned long long a1 = mul2(qq[1], v0.y);
    fma2(a0, qq[0], v0.x);
    fma2(a1, qq[3], v1.y);
    fma2(a0, qq[2], v1.x);
    fma2(a1, qq[5], v2.y);
    fma2(a0, qq[4], v2.x);
    fma2(a1, qq[7], v3.y);
    fma2(a0, qq[6], v3.x);
    unsigned long long s = add2(a0, a1);
    float lo, hi;
    unpack2(s, lo, hi);
    return lo + hi;
}

// paired drain in s-space: lanes 0..15 hold list for sLo's query, 16..31 for sHi's.
// Lists sorted DESCENDING in s (= ascending dist). Lazy threshold refresh at exit.
__device__ __forceinline__ void drain_pair_s(float& ls, int& li,
                                             float sLo, float sHi,
                                             float& tLo, float& tHi,
                                             int idx0, bool loHalf, int lane) {
    const unsigned FULL = 0xFFFFFFFFu;
    unsigned ballA = __ballot_sync(FULL, sLo > tLo);
    unsigned ballB = __ballot_sync(FULL, sHi > tHi);
    if (!(ballA | ballB)) return;
    while (ballA | ballB) {
        const bool hasA = (ballA != 0), hasB = (ballB != 0);
        const int bA = hasA ? (__ffs(ballA) - 1) : 0;
        const int bB = hasB ? (__ffs(ballB) - 1) : 0;
        ballA &= ballA - 1;
        ballB &= ballB - 1;
        const float svA = __shfl_sync(FULL, sLo, bA);
        const float svB = __shfl_sync(FULL, sHi, bB);
        const float sv = loHalf ? svA : svB;
        const int   iv = idx0 + (loHalf ? bA : bB);
        const bool valid = loHalf ? hasA : hasB;
        const float pv = __shfl_up_sync(FULL, ls, 1);
        const int   pi = __shfl_up_sync(FULL, li, 1);
        const bool lt  = (ls < sv);                       // strict: ties keep earlier idx
        const bool plt = (lane != 0 && lane != KK) && (pv < sv);
        if (valid && lt) {
            ls = plt ? pv : sv;
            li = plt ? pi : iv;
        }
    }
    tLo = __shfl_sync(FULL, ls, KK - 1);
    tHi = __shfl_sync(FULL, ls, 31);
}

__global__ __launch_bounds__(TPB, 2)
void knn_warp4(const float* __restrict__ x, float* __restrict__ out,
               long long out_elems) {
    __shared__ float sc[TILE * ROWP];
    __shared__ float sch[TILE];

    const int tid  = threadIdx.x;
    const int lane = tid & 31;
    const int wid  = tid >> 5;

    const int qbase = blockIdx.x * QPC;
    const int q0r   = qbase + QPW * wid;
    const int set   = q0r / NPTS;
    const int row0  = q0r - set * NPTS;
    const float* __restrict__ xs = x + (size_t)set * NPTS * DF;

    unsigned long long qqA[8], qqB[8], qqC[8], qqD[8];
    float qhA, qhB, qhC, qhD;
    load_query(xs, row0 + 0, qqA, qhA);
    load_query(xs, row0 + 1, qqB, qhB);
    load_query(xs, row0 + 2, qqC, qhC);
    load_query(xs, row0 + 3, qqD, qhD);

    // layer1: lanes 0-15 = list A, lanes 16-31 = list B (s-space, descending)
    // layer2: lanes 0-15 = list C, lanes 16-31 = list D
    float l1_s = -FLT_MAX, l2_s = -FLT_MAX;
    int   l1_i = 0,        l2_i = 0;
    float thrA = -FLT_MAX, thrB = -FLT_MAX, thrC = -FLT_MAX, thrD = -FLT_MAX;
    const bool loHalf = (lane < KK);

    const float* laneC = sc + lane * ROWP;   // this lane's candidate row base
    for (int j0 = 0; j0 < NPTS; j0 += TILE) {
        __syncthreads();
        {
            const float4* src = reinterpret_cast<const float4*>(xs + (size_t)(j0 + tid) * DF);
            float4 c0 = src[0], c1 = src[1], c2 = src[2], c3 = src[3];
            float* dst = sc + tid * ROWP;
            *reinterpret_cast<float4*>(dst)      = c0;
            *reinterpret_cast<float4*>(dst + 4)  = c1;
            *reinterpret_cast<float4*>(dst + 8)  = c2;
            *reinterpret_cast<float4*>(dst + 12) = c3;
            float n = c0.x*c0.x + c0.y*c0.y + c0.z*c0.z + c0.w*c0.w
                    + c1.x*c1.x + c1.y*c1.y + c1.z*c1.z + c1.w*c1.w
                    + c2.x*c2.x + c2.y*c2.y + c2.z*c2.z + c2.w*c2.w
                    + c3.x*c3.x + c3.y*c3.y + c3.z*c3.z + c3.w*c3.w;
            sch[tid] = -0.5f * n;
        }
        __syncthreads();

        // software pipeline: u/ch hold candidate for current sub; prefetch next
        ulonglong2 u0, u1, u2, u3;
        float ch;
        {
            const ulonglong2* cp = reinterpret_cast<const ulonglong2*>(laneC);
            u0 = cp[0]; u1 = cp[1]; u2 = cp[2]; u3 = cp[3];
            ch = sch[lane];
        }
#pragma unroll
        for (int sub = 0; sub < SUBS; ++sub) {
            float sA = s_one(qqA, qhA, u0, u1, u2, u3, ch);
            float sB = s_one(qqB, qhB, u0, u1, u2, u3, ch);
            float sC = s_one(qqC, qhC, u0, u1, u2, u3, ch);
            float sD = s_one(qqD, qhD, u0, u1, u2, u3, ch);

            // prefetch next candidate into the (now dead) u regs — LDS latency
            // is covered by the drain collectives below.
            if (sub + 1 < SUBS) {
                const ulonglong2* cp =
                    reinterpret_cast<const ulonglong2*>(laneC + (sub + 1) * 32 * ROWP);
                u0 = cp[0]; u1 = cp[1]; u2 = cp[2]; u3 = cp[3];
                ch = sch[(sub + 1) * 32 + lane];
            }

            const int idx0 = j0 + sub * 32;
            drain_pair_s(l1_s, l1_i, sA, sB, thrA, thrB, idx0, loHalf, lane);
            drain_pair_s(l2_s, l2_i, sC, sD, thrC, thrD, idx0, loHalf, lane);
        }
    }

    // write outputs directly (dist = -2*s, identical float value to before)
    const long long E = (long long)NSETS * NPTS * KK;
    const int p    = loHalf ? lane : (lane - KK);
    const int qr1  = loHalf ? (q0r + 0) : (q0r + 1);
    const int qr2  = loHalf ? (q0r + 2) : (q0r + 3);
    const float d1 = -2.0f * l1_s;
    const float d2 = -2.0f * l2_s;
    if (out_elems >= 3 * E) {
        long long b1 = (long long)qr1 * KK + p;
        out[b1]         = (float)qr1;
        out[E + b1]     = (float)(set * NPTS + l1_i);
        out[2 * E + b1] = d1;
        long long b2 = (long long)qr2 * KK + p;
        out[b2]         = (float)qr2;
        out[E + b2]     = (float)(set * NPTS + l2_i);
        out[2 * E + b2] = d2;
    } else {
        out[(long long)qr1 * KK + p] = d1;
        out[(long long)qr2 * KK + p] = d2;
    }
}

extern "C" void kernel_launch(void* const* d_in, const int* in_sizes, int n_in,
                              void* d_out, int out_size) {
    const float* x = (const float*)d_in[0];
    float* out = (float*)d_out;
    knn_warp4<<<(NSETS * NPTS) / QPC, TPB>>>(x, out, (long long)out_size);
}